// round 13
// baseline (speedup 1.0000x reference)
#include <cuda_runtime.h>

// Shapes: B=32, N=128, IN_CH=16, IN_DIM=32, OUT_CH=32, OUT_DIM=32, P=2048
// x[b,n,c,i]  : b*65536 + n*512 + c*32 + i
// W[c,o,i,j]  : c*32768 + o*1024 + i*32 + j
// y/z[b,o,c,i]: (b*32+o)*512 + c*32 + i
// b_ij is linear in the z-history: b_t = x . (z_0+..+z_{t-1}); never materialized.
// Single persistent kernel, grid 128 (all co-resident), software grid barriers.

typedef unsigned long long u64;

__device__ __forceinline__ u64 pk(float a, float b) {
    u64 r; asm("mov.b64 %0,{%1,%2};" : "=l"(r) : "f"(a), "f"(b)); return r;
}
__device__ __forceinline__ void upk(u64 p, float& a, float& b) {
    asm("mov.b64 {%0,%1},%2;" : "=f"(a), "=f"(b) : "l"(p));
}
__device__ __forceinline__ void fma2(u64& d, u64 a, u64 b) {
    asm("fma.rn.f32x2 %0,%1,%2,%0;" : "+l"(d) : "l"(a), "l"(b));
}
__device__ __forceinline__ u64 add2(u64 a, u64 b) {
    u64 r; asm("add.rn.f32x2 %0,%1,%2;" : "=l"(r) : "l"(a), "l"(b)); return r;
}

__device__ __align__(16) float g_y  [32*32*16*32];
__device__ __align__(16) float g_y0p[32*8*512];
__device__ __align__(16) float g_z  [32*32*16*32];
__device__ float g_sp [32*16*32];
__device__ float g_mp [32*16*32];
__device__ float g_t  [32*32];
__device__ unsigned g_bar[8];

#define NBLK 128

__global__ void k_init()
{
    if (threadIdx.x < 8) g_bar[threadIdx.x] = 0u;
}

__device__ __forceinline__ void gridbar(int k)
{
    __syncthreads();
    if (threadIdx.x == 0) {
        __threadfence();
        atomicAdd(&g_bar[k], 1u);
        volatile unsigned* p = &g_bar[k];
        while (*p < NBLK) __nanosleep(64);
        __threadfence();
    }
    __syncthreads();
}

// smem word offsets
#define OFF_W   0          // persistent W [512][36]
#define OFF_U   18432      // union scratch
// k_s view:  y2 = U (u64[2048] = 8192 w), part = U+8192 ([16][264]), v = U+12416 ([8][36])
// k_f view:  x = U (4096), w = U+4096 ([128][36]), z = U+8704 ([32][34]),
//            mred = U+9792, sred = U+10320, toff = U+10848, yred = U+10880 (u64[512])
#define SMEM_TOTAL ((18432 + 12704) * 4)

__global__ __launch_bounds__(512) void k_main(const float* __restrict__ x,
                                              const float* __restrict__ Wg,
                                              float* __restrict__ out)
{
    extern __shared__ __align__(16) float sm[];
    float* W36 = sm + OFF_W;
    float* U   = sm + OFF_U;

    const int bid = blockIdx.x;
    const int t = threadIdx.x, lane = t & 31, wid = t >> 5;
    const int o  = bid & 31;          // k_s role
    const int b0 = (bid >> 5) * 8;    // k_s role

    // ================= P0: W -> smem (once) + y0 partials =================
    {
        const float4* W4 = (const float4*)Wg;
        #pragma unroll
        for (int k = 0; k < 8; ++k) {
            int gi = k*512 + t;
            int c = gi >> 8, tt = gi & 255;
            float4 w = W4[c*8192 + o*256 + tt];
            int i = tt >> 3, j0 = (tt & 7) * 4;
            *(float4*)(W36 + (c*32 + i)*36 + j0) = w;
        }
        #pragma unroll
        for (int q = 0; q < 2; ++q) {
            int u = bid*2 + q;
            int b = u >> 3, k = u & 7;
            const float* xb = x + b*65536 + k*16*512 + t;
            float acc = 0.f;
            #pragma unroll
            for (int n = 0; n < 16; ++n) acc += xb[n*512];
            g_y0p[b*4096 + k*512 + t] = acc * (1.f/2048.f);
        }
    }
    gridbar(0);

    // ================= k_s phases (W already resident) =====================
    #define KS_PHASE(MODE)                                                       \
    {                                                                            \
        u64*   y2   = (u64*)U;                                                   \
        float* part = U + 8192;                                                  \
        float* v_sm = U + 12416;                                                 \
        {                                                                        \
            int bp = t >> 7, ci4 = t & 127;                                      \
            float4 A, Bv;                                                        \
            if (MODE == 0) {                                                     \
                const float4* pa = (const float4*)g_y0p + (b0+2*bp  )*1024 + ci4;\
                const float4* pb = (const float4*)g_y0p + (b0+2*bp+1)*1024 + ci4;\
                A = pa[0]; Bv = pb[0];                                           \
                _Pragma("unroll")                                                \
                for (int k = 1; k < 8; ++k) {                                    \
                    float4 uu = pa[k*128], vv = pb[k*128];                       \
                    A.x+=uu.x; A.y+=uu.y; A.z+=uu.z; A.w+=uu.w;                  \
                    Bv.x+=vv.x; Bv.y+=vv.y; Bv.z+=vv.z; Bv.w+=vv.w;              \
                }                                                                \
            } else {                                                             \
                A  = ((const float4*)(g_y + (b0+2*bp  )*16384 + o*512))[ci4];    \
                Bv = ((const float4*)(g_y + (b0+2*bp+1)*16384 + o*512))[ci4];    \
            }                                                                    \
            u64* dst = y2 + bp*512 + ci4*4;                                      \
            dst[0] = pk(A.x, Bv.x); dst[1] = pk(A.y, Bv.y);                      \
            dst[2] = pk(A.z, Bv.z); dst[3] = pk(A.w, Bv.w);                      \
        }                                                                        \
        __syncthreads();                                                         \
        int j = t & 31, w5 = t >> 5;                                             \
        int ci_base = w5 * 32;                                                   \
        u64 acc2[4] = {0,0,0,0};                                                 \
        _Pragma("unroll 2")                                                      \
        for (int g = 0; g < 8; ++g) {                                            \
            int ci0 = ci_base + g*4;                                             \
            const float* wp = W36 + ci0*36 + j;                                  \
            float w0 = wp[0], w1 = wp[36], w2 = wp[72], w3 = wp[108];            \
            u64 p0 = pk(w0,w0), p1 = pk(w1,w1), p2 = pk(w2,w2), p3 = pk(w3,w3);  \
            _Pragma("unroll")                                                    \
            for (int bp = 0; bp < 4; ++bp) {                                     \
                const ulonglong2* yy = (const ulonglong2*)(y2 + bp*512 + ci0);   \
                ulonglong2 ya = yy[0], yb = yy[1];                               \
                fma2(acc2[bp], ya.x, p0);                                        \
                fma2(acc2[bp], ya.y, p1);                                        \
                fma2(acc2[bp], yb.x, p2);                                        \
                fma2(acc2[bp], yb.y, p3);                                        \
            }                                                                    \
        }                                                                        \
        _Pragma("unroll")                                                        \
        for (int bp = 0; bp < 4; ++bp) {                                         \
            float sa, sb; upk(acc2[bp], sa, sb);                                 \
            part[w5*264 + (2*bp  )*33 + j] = sa;                                 \
            part[w5*264 + (2*bp+1)*33 + j] = sb;                                 \
        }                                                                        \
        __syncthreads();                                                         \
        if (w5 < 8) {                                                            \
            int b = b0 + w5;                                                     \
            float sacc = 0.f;                                                    \
            _Pragma("unroll")                                                    \
            for (int e = 0; e < 16; ++e) sacc += part[e*264 + w5*33 + j];        \
            float Sinv = 1.f;                                                    \
            if (MODE != 0) {                                                     \
                float sv = (j < 16) ? g_sp[b*512 + j*32 + o] : 0.f;              \
                _Pragma("unroll")                                                \
                for (int s2 = 16; s2; s2 >>= 1)                                  \
                    sv += __shfl_xor_sync(0xffffffffu, sv, s2);                  \
                Sinv = 1.f / sv;                                                 \
                if (MODE == 1) {                                                 \
                    float mv = (j < 16) ? g_mp[b*512 + j*32 + o] : -1e30f;       \
                    _Pragma("unroll")                                            \
                    for (int s2 = 16; s2; s2 >>= 1)                              \
                        mv = fmaxf(mv, __shfl_xor_sync(0xffffffffu, mv, s2));    \
                    if (j == 0) g_t[b*32 + o] = mv;                              \
                }                                                                \
            }                                                                    \
            float acc = sacc * Sinv;                                             \
            float mag_sq = acc*acc;                                              \
            _Pragma("unroll")                                                    \
            for (int s2 = 16; s2; s2 >>= 1)                                      \
                mag_sq += __shfl_xor_sync(0xffffffffu, mag_sq, s2);              \
            float mag = sqrtf(mag_sq) + 1e-11f;                                  \
            float a   = mag_sq / (1.f + mag_sq);                                 \
            float v   = acc * (a / mag);                                         \
            v_sm[w5*36 + j] = v;                                                 \
            if (MODE == 2) {                                                     \
                out[(b*32 + o)*32 + j] = v;                                      \
                if (j == 0) out[32768 + b*32 + o] = a;                           \
            }                                                                    \
        }                                                                        \
        if (MODE != 2) {                                                         \
            __syncthreads();                                                     \
            int lb = j & 7, lc = j >> 3;                                         \
            u64 vp[16];                                                          \
            const ulonglong2* vv = (const ulonglong2*)(v_sm + lb*36);            \
            _Pragma("unroll")                                                    \
            for (int q = 0; q < 8; ++q) {                                        \
                ulonglong2 uu = vv[q]; vp[2*q] = uu.x; vp[2*q+1] = uu.y;         \
            }                                                                    \
            float* zrow = g_z + ((b0 + lb)*32 + o)*512;                          \
            _Pragma("unroll")                                                    \
            for (int it = 0; it < 8; ++it) {                                     \
                int ci = ci_base + it*4 + lc;                                    \
                const ulonglong2* wr = (const ulonglong2*)(W36 + ci*36);         \
                u64 d = 0;                                                       \
                _Pragma("unroll")                                                \
                for (int q = 0; q < 8; ++q) {                                    \
                    ulonglong2 wq = wr[q];                                       \
                    fma2(d, wq.x, vp[2*q]);                                      \
                    fma2(d, wq.y, vp[2*q+1]);                                    \
                }                                                                \
                float zl, zh; upk(d, zl, zh);                                    \
                float z = zl + zh;                                               \
                if (MODE == 1) z += zrow[ci];                                    \
                zrow[ci] = z;                                                    \
            }                                                                    \
        }                                                                        \
    }

    // ================= k_f phase: 4 (b,c) tiles per block ==================
    #define KF_PHASE(USE_TOFF, WRITE_MP)                                         \
    {                                                                            \
        float* x_sm = U;                                                         \
        float* w_sm = U + 4096;                                                  \
        float* z_sm = U + 8704;                                                  \
        float* mred = U + 9792;                                                  \
        float* sred = U + 10320;                                                 \
        float* toff_sm = U + 10848;                                              \
        u64*   yred = (u64*)(U + 10880);                                         \
        for (int q4 = 0; q4 < 4; ++q4) {                                         \
            int tile = bid*4 + q4;                                               \
            int b = tile >> 4, c = tile & 15;                                    \
            const float* xb = x + b*65536 + c*32;                                \
            _Pragma("unroll")                                                    \
            for (int nn = 0; nn < 8; ++nn) {                                     \
                int n = wid*8 + nn;                                              \
                x_sm[n*32 + lane] = xb[n*512 + lane];                            \
            }                                                                    \
            {                                                                    \
                int oo = t >> 4, i2 = t & 15;                                    \
                float2 vv = *(const float2*)(g_z + (b*32+oo)*512 + c*32 + 2*i2); \
                *(float2*)(z_sm + oo*34 + 2*i2) = vv;                            \
            }                                                                    \
            if (t < 32) toff_sm[t] = USE_TOFF ? g_t[b*32 + t] : 0.f;             \
            __syncthreads();                                                     \
            u64 zr[16];                                                          \
            _Pragma("unroll")                                                    \
            for (int q = 0; q < 16; ++q)                                         \
                zr[q] = *(const u64*)(z_sm + lane*34 + 2*q);                     \
            float toff = toff_sm[lane];                                          \
            float bmax = -1e30f, ssum = 0.f;                                     \
            _Pragma("unroll")                                                    \
            for (int nn = 0; nn < 8; ++nn) {                                     \
                int n = wid*8 + nn;                                              \
                const ulonglong2* xr = (const ulonglong2*)(x_sm + n*32);         \
                u64 a0 = 0, a1 = 0;                                              \
                _Pragma("unroll")                                                \
                for (int q = 0; q < 8; ++q) {                                    \
                    ulonglong2 xv = xr[q];                                       \
                    fma2(a0, xv.x, zr[2*q]);                                     \
                    fma2(a1, xv.y, zr[2*q+1]);                                   \
                }                                                                \
                float l0,h0,l1,h1; upk(a0,l0,h0); upk(a1,l1,h1);                 \
                float du = (l0+h0)+(l1+h1);                                      \
                bmax = fmaxf(bmax, du);                                          \
                float w = __expf(du - toff);                                     \
                ssum += w;                                                       \
                w_sm[n*36 + lane] = w;                                           \
            }                                                                    \
            mred[wid*33 + lane] = bmax;                                          \
            sred[wid*33 + lane] = ssum;                                          \
            __syncthreads();                                                     \
            if (t < 32) {                                                        \
                float m = -1e30f, s = 0.f;                                       \
                _Pragma("unroll")                                                \
                for (int g = 0; g < 16; ++g) {                                   \
                    m = fmaxf(m, mred[g*33 + t]);                                \
                    s += sred[g*33 + t];                                         \
                }                                                                \
                if (WRITE_MP) g_mp[b*512 + c*32 + t] = m;                        \
                g_sp[b*512 + c*32 + t] = s;                                      \
            }                                                                    \
            int oq = wid & 7, nh = wid >> 3, o0 = oq*4;                          \
            u64 acc0 = 0, acc1 = 0;                                              \
            _Pragma("unroll 4")                                                  \
            for (int nn = 0; nn < 64; ++nn) {                                    \
                int n = nh*64 + nn;                                              \
                float xv = x_sm[n*32 + lane];                                    \
                ulonglong2 wv = *(const ulonglong2*)(w_sm + n*36 + o0);          \
                u64 xs = pk(xv, xv);                                             \
                fma2(acc0, wv.x, xs);                                            \
                fma2(acc1, wv.y, xs);                                            \
            }                                                                    \
            if (nh == 1) {                                                       \
                yred[(oq*2+0)*32 + lane] = acc0;                                 \
                yred[(oq*2+1)*32 + lane] = acc1;                                 \
            }                                                                    \
            __syncthreads();                                                     \
            if (nh == 0) {                                                       \
                acc0 = add2(acc0, yred[(oq*2+0)*32 + lane]);                     \
                acc1 = add2(acc1, yred[(oq*2+1)*32 + lane]);                     \
                float p0,p1,p2,p3; upk(acc0,p0,p1); upk(acc1,p2,p3);             \
                float* ybp = g_y + b*16384 + c*32 + lane;                        \
                ybp[(o0  )*512] = p0; ybp[(o0+1)*512] = p1;                      \
                ybp[(o0+2)*512] = p2; ybp[(o0+3)*512] = p3;                      \
            }                                                                    \
            __syncthreads();                                                     \
        }                                                                        \
    }

    KS_PHASE(0)            // P1: v0, z_cum = z0
    gridbar(1);
    KF_PHASE(0, 1)         // P2: y1, S + max partials
    gridbar(2);
    KS_PHASE(1)            // P3: v1, z_cum += z1, g_t
    gridbar(3);
    KF_PHASE(1, 0)         // P4: y2, S
    gridbar(4);
    KS_PHASE(2)            // P5: v2, a2 -> out
}

// ---------------------------------------------------------------------------
extern "C" void kernel_launch(void* const* d_in, const int* in_sizes, int n_in,
                              void* d_out, int out_size)
{
    const float* x = (const float*)d_in[0];
    const float* W = (const float*)(n_in > 1 ? d_in[1] : d_in[0]);
    for (int i = 0; i < n_in; ++i) {
        if (in_sizes[i] == 32*128*16*32)      x = (const float*)d_in[i];
        else if (in_sizes[i] == 16*32*32*32)  W = (const float*)d_in[i];
    }
    float* out = (float*)d_out;

    cudaFuncSetAttribute(k_main, cudaFuncAttributeMaxDynamicSharedMemorySize,
                         SMEM_TOTAL);

    k_init<<<1, 32>>>();
    k_main<<<NBLK, 512, SMEM_TOTAL>>>(x, W, out);
}

// round 14
// speedup vs baseline: 1.0395x; 1.0395x over previous
#include <cuda_runtime.h>

// Shapes: B=32, N=128, IN_CH=16, IN_DIM=32, OUT_CH=32, OUT_DIM=32, P=2048
// x[b,n,c,i]  : b*65536 + n*512 + c*32 + i
// W[c,o,i,j]  : c*32768 + o*1024 + i*32 + j
// y/z[b,o,c,i]: (b*32+o)*512 + c*32 + i
// b_ij is linear in the z-history: b_t = x . (z_0+..+z_{t-1}); never materialized.
// Persistent kernel, grid 256 (2 blocks/SM, all co-resident), grid barriers.

typedef unsigned long long u64;

__device__ __forceinline__ u64 pk(float a, float b) {
    u64 r; asm("mov.b64 %0,{%1,%2};" : "=l"(r) : "f"(a), "f"(b)); return r;
}
__device__ __forceinline__ void upk(u64 p, float& a, float& b) {
    asm("mov.b64 {%0,%1},%2;" : "=f"(a), "=f"(b) : "l"(p));
}
__device__ __forceinline__ void fma2(u64& d, u64 a, u64 b) {
    asm("fma.rn.f32x2 %0,%1,%2,%0;" : "+l"(d) : "l"(a), "l"(b));
}
__device__ __forceinline__ u64 add2(u64 a, u64 b) {
    u64 r; asm("add.rn.f32x2 %0,%1,%2;" : "=l"(r) : "l"(a), "l"(b)); return r;
}

__device__ __align__(16) float g_y  [32*32*16*32];
__device__ __align__(16) float g_y0p[32*8*512];
__device__ __align__(16) float g_z  [32*32*16*32];
__device__ float g_sp [32*16*32];
__device__ float g_mp [32*16*32];
__device__ float g_t  [32*32];
__device__ unsigned g_bar[8];

#define NBLK 256

__global__ void k_init()
{
    if (threadIdx.x < 8) g_bar[threadIdx.x] = 0u;
}

__device__ __forceinline__ void gridbar(int k)
{
    __syncthreads();
    if (threadIdx.x == 0) {
        __threadfence();
        atomicAdd(&g_bar[k], 1u);
        volatile unsigned* p = &g_bar[k];
        while (*p < NBLK) __nanosleep(64);
        __threadfence();
    }
    __syncthreads();
}

// smem (one allocation, two phase views):
// KS view: W36 = sm [512][36] (18432), y2 = +18432 (u64[1024] = 2048w),
//          part = +20480 ([16][132] = 2112w), v = +22592 ([4][36] = 144w)
// KF view: x = sm (4096), w = +4096 ([128][36]), z = +8704 ([32][34]),
//          mred = +9792, sred = +10320, toff = +10848, pred = +10880 (u64[1536])
#define SMEM_TOTAL (22736 * 4)

__global__ __launch_bounds__(512, 2) void k_main(const float* __restrict__ x,
                                                 const float* __restrict__ Wg,
                                                 float* __restrict__ out)
{
    extern __shared__ __align__(16) float sm[];

    const int bid = blockIdx.x;
    const int t = threadIdx.x, lane = t & 31, wid = t >> 5;
    const int o  = bid & 31;          // KS role
    const int b0 = (bid >> 5) * 4;    // KS role: 4 b's per block

    // ================= P0: y0 partials (1 unit per block) ==================
    {
        int b = bid >> 3, k = bid & 7;
        const float* xb = x + b*65536 + k*16*512 + t;
        float acc = 0.f;
        #pragma unroll
        for (int n = 0; n < 16; ++n) acc += xb[n*512];
        g_y0p[b*4096 + k*512 + t] = acc * (1.f/2048.f);
    }
    gridbar(0);

    // ================= KS phase ===========================================
    #define KS_PHASE(MODE)                                                       \
    {                                                                            \
        float* W36  = sm;                                                        \
        u64*   y2   = (u64*)(sm + 18432);                                        \
        float* part = sm + 20480;                                                \
        float* v_sm = sm + 22592;                                                \
        const float4* W4 = (const float4*)Wg;                                    \
        _Pragma("unroll")                                                        \
        for (int k = 0; k < 8; ++k) {                                            \
            int gi = k*512 + t;                                                  \
            int c = gi >> 8, tt = gi & 255;                                      \
            float4 w = W4[c*8192 + o*256 + tt];                                  \
            int i = tt >> 3, j0 = (tt & 7) * 4;                                  \
            *(float4*)(W36 + (c*32 + i)*36 + j0) = w;                            \
        }                                                                        \
        if (t < 256) {                                                           \
            int bp = t >> 7, ci4 = t & 127;                                      \
            float4 A, Bv;                                                        \
            if (MODE == 0) {                                                     \
                const float4* pa = (const float4*)g_y0p + (b0+2*bp  )*1024 + ci4;\
                const float4* pb = (const float4*)g_y0p + (b0+2*bp+1)*1024 + ci4;\
                A = pa[0]; Bv = pb[0];                                           \
                _Pragma("unroll")                                                \
                for (int k = 1; k < 8; ++k) {                                    \
                    float4 uu = pa[k*128], vv = pb[k*128];                       \
                    A.x+=uu.x; A.y+=uu.y; A.z+=uu.z; A.w+=uu.w;                  \
                    Bv.x+=vv.x; Bv.y+=vv.y; Bv.z+=vv.z; Bv.w+=vv.w;              \
                }                                                                \
            } else {                                                             \
                A  = ((const float4*)(g_y + (b0+2*bp  )*16384 + o*512))[ci4];    \
                Bv = ((const float4*)(g_y + (b0+2*bp+1)*16384 + o*512))[ci4];    \
            }                                                                    \
            u64* dst = y2 + bp*512 + ci4*4;                                      \
            dst[0] = pk(A.x, Bv.x); dst[1] = pk(A.y, Bv.y);                      \
            dst[2] = pk(A.z, Bv.z); dst[3] = pk(A.w, Bv.w);                      \
        }                                                                        \
        __syncthreads();                                                         \
        int j = t & 31, w5 = t >> 5;                                             \
        int ci_base = w5 * 32;                                                   \
        u64 acc2[2] = {0,0};                                                     \
        _Pragma("unroll 2")                                                      \
        for (int g = 0; g < 8; ++g) {                                            \
            int ci0 = ci_base + g*4;                                             \
            const float* wp = W36 + ci0*36 + j;                                  \
            float w0 = wp[0], w1 = wp[36], w2 = wp[72], w3 = wp[108];            \
            u64 p0 = pk(w0,w0), p1 = pk(w1,w1), p2 = pk(w2,w2), p3 = pk(w3,w3);  \
            _Pragma("unroll")                                                    \
            for (int bp = 0; bp < 2; ++bp) {                                     \
                const ulonglong2* yy = (const ulonglong2*)(y2 + bp*512 + ci0);   \
                ulonglong2 ya = yy[0], yb = yy[1];                               \
                fma2(acc2[bp], ya.x, p0);                                        \
                fma2(acc2[bp], ya.y, p1);                                        \
                fma2(acc2[bp], yb.x, p2);                                        \
                fma2(acc2[bp], yb.y, p3);                                        \
            }                                                                    \
        }                                                                        \
        _Pragma("unroll")                                                        \
        for (int bp = 0; bp < 2; ++bp) {                                         \
            float sa, sb; upk(acc2[bp], sa, sb);                                 \
            part[w5*132 + (2*bp  )*33 + j] = sa;                                 \
            part[w5*132 + (2*bp+1)*33 + j] = sb;                                 \
        }                                                                        \
        __syncthreads();                                                         \
        if (w5 < 4) {                                                            \
            int b = b0 + w5;                                                     \
            float sacc = 0.f;                                                    \
            _Pragma("unroll")                                                    \
            for (int e = 0; e < 16; ++e) sacc += part[e*132 + w5*33 + j];        \
            float Sinv = 1.f;                                                    \
            if (MODE != 0) {                                                     \
                float sv = (j < 16) ? g_sp[b*512 + j*32 + o] : 0.f;              \
                _Pragma("unroll")                                                \
                for (int s2 = 16; s2; s2 >>= 1)                                  \
                    sv += __shfl_xor_sync(0xffffffffu, sv, s2);                  \
                Sinv = 1.f / sv;                                                 \
                if (MODE == 1) {                                                 \
                    float mv = (j < 16) ? g_mp[b*512 + j*32 + o] : -1e30f;       \
                    _Pragma("unroll")                                            \
                    for (int s2 = 16; s2; s2 >>= 1)                              \
                        mv = fmaxf(mv, __shfl_xor_sync(0xffffffffu, mv, s2));    \
                    if (j == 0) g_t[b*32 + o] = mv;                              \
                }                                                                \
            }                                                                    \
            float acc = sacc * Sinv;                                             \
            float mag_sq = acc*acc;                                              \
            _Pragma("unroll")                                                    \
            for (int s2 = 16; s2; s2 >>= 1)                                      \
                mag_sq += __shfl_xor_sync(0xffffffffu, mag_sq, s2);              \
            float mag = sqrtf(mag_sq) + 1e-11f;                                  \
            float a   = mag_sq / (1.f + mag_sq);                                 \
            float v   = acc * (a / mag);                                         \
            v_sm[w5*36 + j] = v;                                                 \
            if (MODE == 2) {                                                     \
                out[(b*32 + o)*32 + j] = v;                                      \
                if (j == 0) out[32768 + b*32 + o] = a;                           \
            }                                                                    \
        }                                                                        \
        if (MODE != 2) {                                                         \
            __syncthreads();                                                     \
            int lb = j >> 3, lc = j & 7;                                         \
            u64 vp[16];                                                          \
            const ulonglong2* vv = (const ulonglong2*)(v_sm + lb*36);            \
            _Pragma("unroll")                                                    \
            for (int q = 0; q < 8; ++q) {                                        \
                ulonglong2 uu = vv[q]; vp[2*q] = uu.x; vp[2*q+1] = uu.y;         \
            }                                                                    \
            float* zrow = g_z + ((b0 + lb)*32 + o)*512;                          \
            _Pragma("unroll")                                                    \
            for (int it = 0; it < 4; ++it) {                                     \
                int ci = ci_base + it*8 + lc;                                    \
                const ulonglong2* wr = (const ulonglong2*)(W36 + ci*36);         \
                u64 d = 0;                                                       \
                _Pragma("unroll")                                                \
                for (int q = 0; q < 8; ++q) {                                    \
                    ulonglong2 wq = wr[q];                                       \
                    fma2(d, wq.x, vp[2*q]);                                      \
                    fma2(d, wq.y, vp[2*q+1]);                                    \
                }                                                                \
                float zl, zh; upk(d, zl, zh);                                    \
                float z = zl + zh;                                               \
                if (MODE == 1) z += zrow[ci];                                    \
                zrow[ci] = z;                                                    \
            }                                                                    \
        }                                                                        \
    }

    // ================= KF phase: 2 (b,c) tiles per block ===================
    #define KF_PHASE(USE_TOFF, WRITE_MP)                                         \
    {                                                                            \
        float* x_sm = sm;                                                        \
        float* w_sm = sm + 4096;                                                 \
        float* z_sm = sm + 8704;                                                 \
        float* mred = sm + 9792;                                                 \
        float* sred = sm + 10320;                                                \
        float* toff_sm = sm + 10848;                                             \
        u64*   pred = (u64*)(sm + 10880);                                        \
        for (int q2 = 0; q2 < 2; ++q2) {                                         \
            int tile = bid*2 + q2;                                               \
            int b = tile >> 4, c = tile & 15;                                    \
            const float* xb = x + b*65536 + c*32;                                \
            _Pragma("unroll")                                                    \
            for (int nn = 0; nn < 8; ++nn) {                                     \
                int n = wid*8 + nn;                                              \
                x_sm[n*32 + lane] = xb[n*512 + lane];                            \
            }                                                                    \
            {                                                                    \
                int oo = t >> 4, i2 = t & 15;                                    \
                float2 vv = *(const float2*)(g_z + (b*32+oo)*512 + c*32 + 2*i2); \
                *(float2*)(z_sm + oo*34 + 2*i2) = vv;                            \
            }                                                                    \
            if (t < 32) toff_sm[t] = USE_TOFF ? g_t[b*32 + t] : 0.f;             \
            __syncthreads();                                                     \
            {                                                                    \
                u64 zr[16];                                                      \
                _Pragma("unroll")                                                \
                for (int q = 0; q < 16; ++q)                                     \
                    zr[q] = *(const u64*)(z_sm + lane*34 + 2*q);                 \
                float toff = toff_sm[lane];                                      \
                float bmax = -1e30f, ssum = 0.f;                                 \
                _Pragma("unroll")                                                \
                for (int nn = 0; nn < 8; ++nn) {                                 \
                    int n = wid*8 + nn;                                          \
                    const ulonglong2* xr = (const ulonglong2*)(x_sm + n*32);     \
                    u64 a0 = 0, a1 = 0;                                          \
                    _Pragma("unroll")                                            \
                    for (int q = 0; q < 8; ++q) {                                \
                        ulonglong2 xv = xr[q];                                   \
                        fma2(a0, xv.x, zr[2*q]);                                 \
                        fma2(a1, xv.y, zr[2*q+1]);                               \
                    }                                                            \
                    float l0,h0,l1,h1; upk(a0,l0,h0); upk(a1,l1,h1);             \
                    float du = (l0+h0)+(l1+h1);                                  \
                    bmax = fmaxf(bmax, du);                                      \
                    float w = __expf(du - toff);                                 \
                    ssum += w;                                                   \
                    w_sm[n*36 + lane] = w;                                       \
                }                                                                \
                mred[wid*33 + lane] = bmax;                                      \
                sred[wid*33 + lane] = ssum;                                      \
            }                                                                    \
            __syncthreads();                                                     \
            if (t < 32) {                                                        \
                float m = -1e30f, s = 0.f;                                       \
                _Pragma("unroll")                                                \
                for (int g = 0; g < 16; ++g) {                                   \
                    m = fmaxf(m, mred[g*33 + t]);                                \
                    s += sred[g*33 + t];                                         \
                }                                                                \
                if (WRITE_MP) g_mp[b*512 + c*32 + t] = m;                        \
                g_sp[b*512 + c*32 + t] = s;                                      \
            }                                                                    \
            {                                                                    \
                int oq = wid & 3, nq = wid >> 2, o0 = oq*8;                      \
                u64 acc[4] = {0,0,0,0};                                          \
                _Pragma("unroll 4")                                              \
                for (int nn = 0; nn < 32; ++nn) {                                \
                    int n = nq*32 + nn;                                          \
                    float xv = x_sm[n*32 + lane];                                \
                    ulonglong2 wv0 = *(const ulonglong2*)(w_sm + n*36 + o0);     \
                    ulonglong2 wv1 = *(const ulonglong2*)(w_sm + n*36 + o0 + 4); \
                    u64 xs = pk(xv, xv);                                         \
                    fma2(acc[0], wv0.x, xs);                                     \
                    fma2(acc[1], wv0.y, xs);                                     \
                    fma2(acc[2], wv1.x, xs);                                     \
                    fma2(acc[3], wv1.y, xs);                                     \
                }                                                                \
                if (nq) {                                                        \
                    _Pragma("unroll")                                            \
                    for (int k = 0; k < 4; ++k)                                  \
                        pred[(((nq-1)*4 + oq)*4 + k)*32 + lane] = acc[k];        \
                }                                                                \
                __syncthreads();                                                 \
                if (nq == 0) {                                                   \
                    _Pragma("unroll")                                            \
                    for (int p = 0; p < 3; ++p)                                  \
                        _Pragma("unroll")                                        \
                        for (int k = 0; k < 4; ++k)                              \
                            acc[k] = add2(acc[k],                                \
                                          pred[((p*4 + oq)*4 + k)*32 + lane]);   \
                    float* ybp = g_y + b*16384 + c*32 + lane;                    \
                    _Pragma("unroll")                                            \
                    for (int k = 0; k < 4; ++k) {                                \
                        float va, vb; upk(acc[k], va, vb);                       \
                        ybp[(o0 + 2*k    )*512] = va;                            \
                        ybp[(o0 + 2*k + 1)*512] = vb;                            \
                    }                                                            \
                }                                                                \
            }                                                                    \
            __syncthreads();                                                     \
        }                                                                        \
    }

    KS_PHASE(0)            // P1: v0, z_cum = z0
    gridbar(1);
    KF_PHASE(0, 1)         // P2: y1, S + max partials
    gridbar(2);
    KS_PHASE(1)            // P3: v1, z_cum += z1, g_t
    gridbar(3);
    KF_PHASE(1, 0)         // P4: y2, S
    gridbar(4);
    KS_PHASE(2)            // P5: v2, a2 -> out
}

// ---------------------------------------------------------------------------
extern "C" void kernel_launch(void* const* d_in, const int* in_sizes, int n_in,
                              void* d_out, int out_size)
{
    const float* x = (const float*)d_in[0];
    const float* W = (const float*)(n_in > 1 ? d_in[1] : d_in[0]);
    for (int i = 0; i < n_in; ++i) {
        if (in_sizes[i] == 32*128*16*32)      x = (const float*)d_in[i];
        else if (in_sizes[i] == 16*32*32*32)  W = (const float*)d_in[i];
    }
    float* out = (float*)d_out;

    cudaFuncSetAttribute(k_main, cudaFuncAttributeMaxDynamicSharedMemorySize,
                         SMEM_TOTAL);

    k_init<<<1, 32>>>();
    k_main<<<NBLK, 512, SMEM_TOTAL>>>(x, W, out);
}

// round 15
// speedup vs baseline: 1.0711x; 1.0304x over previous
#include <cuda_runtime.h>

// Shapes: B=32, N=128, IN_CH=16, IN_DIM=32, OUT_CH=32, OUT_DIM=32, P=2048
// x[b,n,c,i]  : b*65536 + n*512 + c*32 + i
// W[c,o,i,j]  : c*32768 + o*1024 + i*32 + j
// y/z[b,o,c,i]: (b*32+o)*512 + c*32 + i
// b_ij is linear in the z-history: b_t = x . (z_0+..+z_{t-1}); never materialized.
// All-scalar fp32; k_f fuses the du GEMM and the y GEMM (x kept in registers).

typedef unsigned long long u64;

__device__ __forceinline__ u64 pk(float a, float b) {
    u64 r; asm("mov.b64 %0,{%1,%2};" : "=l"(r) : "f"(a), "f"(b)); return r;
}
__device__ __forceinline__ void upk(u64 p, float& a, float& b) {
    asm("mov.b64 {%0,%1},%2;" : "=f"(a), "=f"(b) : "l"(p));
}

__device__ __align__(16) float g_y  [32*32*16*32];
__device__ __align__(16) float g_y0p[32*8*512];
__device__ __align__(16) float g_z  [32*32*16*32];
__device__ float g_sp [32*16*32];
__device__ float g_mp [32*16*32];
__device__ float g_t  [32*32];

// ---------------------------------------------------------------------------
__global__ void k_y0(const float* __restrict__ x)
{
    int b = blockIdx.x >> 3, k = blockIdx.x & 7, t = threadIdx.x;
    const float* xb = x + b*65536 + k*16*512 + t;
    float acc = 0.f;
    #pragma unroll
    for (int n = 0; n < 16; ++n) acc += xb[n*512];
    g_y0p[b*4096 + k*512 + t] = acc * (1.f/2048.f);
}

// ---------------------------------------------------------------------------
// k_f: fused routing step. grid 128, 512 threads, 4 (b,c) tiles per block.
// Per tile: du[n,o] = x[n,:].z[o,:], w = exp(du-toff), and y[o,i] += w*x[n,i]
// computed in ONE pass (x float4s held in registers between the two uses).
// ---------------------------------------------------------------------------
#define SMEM_KF (23136*4)
__global__ __launch_bounds__(512) void k_f(const float* __restrict__ x,
                                           int use_toff, int write_mp)
{
    extern __shared__ __align__(16) float sm[];
    float* x_sm    = sm;            // [128][32]
    float* z_sm    = sm + 4096;     // [32][33]  (stride 33: CF scalar reads)
    float* mred    = sm + 5152;     // [16][33]
    float* sred    = sm + 5680;     // [16][33]
    float* toff_sm = sm + 6208;     // [32]
    u64*   yred    = (u64*)(sm + 6240);  // [(wid*16+q)*33 + lane] : 8447 u64

    const int t = threadIdx.x, lane = t & 31, wid = t >> 5;

    for (int q4 = 0; q4 < 4; ++q4) {
        int tile = blockIdx.x*4 + q4;
        int b = tile >> 4, c = tile & 15;

        const float* xb = x + b*65536 + c*32;
        #pragma unroll
        for (int nn = 0; nn < 8; ++nn) {
            int n = wid*8 + nn;
            x_sm[n*32 + lane] = xb[n*512 + lane];
        }
        {   // z slice, scalar (stride-33 rows)
            int oo = t >> 4, i2 = t & 15;
            const float* zg = g_z + (b*32 + oo)*512 + c*32;
            z_sm[oo*33 + i2]      = zg[i2];
            z_sm[oo*33 + i2 + 16] = zg[i2 + 16];
        }
        if (t < 32) toff_sm[t] = use_toff ? g_t[b*32 + t] : 0.f;
        __syncthreads();

        // z row for o = lane (CF scalar LDS, once per tile)
        float zr[32];
        #pragma unroll
        for (int i = 0; i < 32; ++i) zr[i] = z_sm[lane*33 + i];

        float toff = toff_sm[lane];
        float bmax = -1e30f, ssum = 0.f;
        float yacc[32];
        #pragma unroll
        for (int i = 0; i < 32; ++i) yacc[i] = 0.f;

        #pragma unroll
        for (int nn = 0; nn < 8; ++nn) {
            int n = wid*8 + nn;
            const float4* xr = (const float4*)(x_sm + n*32);  // broadcast
            float4 xq[8];
            float d0 = 0.f, d1 = 0.f, d2 = 0.f, d3 = 0.f;
            #pragma unroll
            for (int k = 0; k < 8; ++k) {
                xq[k] = xr[k];
                d0 = fmaf(xq[k].x, zr[4*k+0], d0);
                d1 = fmaf(xq[k].y, zr[4*k+1], d1);
                d2 = fmaf(xq[k].z, zr[4*k+2], d2);
                d3 = fmaf(xq[k].w, zr[4*k+3], d3);
            }
            float du = (d0+d1)+(d2+d3);
            bmax = fmaxf(bmax, du);
            float w = __expf(du - toff);
            ssum += w;
            #pragma unroll
            for (int k = 0; k < 8; ++k) {       // y[o,i] += w * x[n,i]
                yacc[4*k+0] = fmaf(w, xq[k].x, yacc[4*k+0]);
                yacc[4*k+1] = fmaf(w, xq[k].y, yacc[4*k+1]);
                yacc[4*k+2] = fmaf(w, xq[k].z, yacc[4*k+2]);
                yacc[4*k+3] = fmaf(w, xq[k].w, yacc[4*k+3]);
            }
        }
        mred[wid*33 + lane] = bmax;
        sred[wid*33 + lane] = ssum;
        #pragma unroll
        for (int q = 0; q < 16; ++q)
            yred[(wid*16 + q)*33 + lane] = pk(yacc[2*q], yacc[2*q+1]);
        __syncthreads();

        if (t < 32) {
            float m = -1e30f, s = 0.f;
            #pragma unroll
            for (int g = 0; g < 16; ++g) {
                m = fmaxf(m, mred[g*33 + t]);
                s += sred[g*33 + t];
            }
            if (write_mp) g_mp[b*512 + c*32 + t] = m;
            g_sp[b*512 + c*32 + t] = s;
        }
        {   // y reduction: thread (o = t>>4, q = t&15) sums 16 warp partials
            int o = t >> 4, q = t & 15;
            float a = 0.f, bv = 0.f;
            #pragma unroll
            for (int w = 0; w < 16; ++w) {
                float ua, ub; upk(yred[(w*16 + q)*33 + o], ua, ub);
                a += ua; bv += ub;
            }
            float2* yp = (float2*)(g_y + (b*32 + o)*512 + c*32) + q;
            *yp = make_float2(a, bv);
        }
        __syncthreads();
    }
}

// ---------------------------------------------------------------------------
// k_s: s[b,o,j] = (1/S) sum_ci y[b,o,ci] W[ci,o,j]; squash -> v,a;
//      z_cum[b,o,ci] (+)= sum_j W[ci,o,j] v[b,o,j]
// grid 128 (o | b-group of 8), 512 threads. W loaded once (coalesced),
// consumed once by s-loop (reused over 8 b) and once by z-loop. All scalar.
// ---------------------------------------------------------------------------
#define SMEM_KS (27040*4)
__global__ __launch_bounds__(512) void k_s(const float* __restrict__ Wg,
                                           int mode, float* __restrict__ out)
{
    extern __shared__ __align__(16) float sm[];
    float* W36  = sm;              // [512][36]
    float* y_sm = sm + 18432;      // [8][512]
    float* part = sm + 22528;      // [16][8][33]
    float* v_sm = sm + 26752;      // [8][36]

    int o  = blockIdx.x & 31;
    int b0 = (blockIdx.x >> 5) * 8;
    int t  = threadIdx.x;

    // W o-slice, coalesced -> [ci][36]
    const float4* W4 = (const float4*)Wg;
    #pragma unroll
    for (int k = 0; k < 8; ++k) {
        int gi = k*512 + t;
        int c = gi >> 8, tt = gi & 255;
        float4 w = W4[c*8192 + o*256 + tt];
        int i = tt >> 3, j0 = (tt & 7) * 4;
        *(float4*)(W36 + (c*32 + i)*36 + j0) = w;
    }
    // y for 8 b's
    #pragma unroll
    for (int q = 0; q < 2; ++q) {
        int idx = q*512 + t, bb = idx >> 7, ci4 = idx & 127;
        float4 val;
        if (mode == 0) {
            const float4* yp = (const float4*)g_y0p + (b0+bb)*1024 + ci4;
            val = yp[0];
            #pragma unroll
            for (int k = 1; k < 8; ++k) {
                float4 v = yp[k*128];
                val.x += v.x; val.y += v.y; val.z += v.z; val.w += v.w;
            }
        } else {
            val = ((const float4*)(g_y + (b0+bb)*16384 + o*512))[ci4];
        }
        *(float4*)(y_sm + bb*512 + ci4*4) = val;
    }
    __syncthreads();

    int j = t & 31, w5 = t >> 5;
    int ci_base = w5 * 32;

    // s-loop: warp owns 32-ci strip for all 8 b; scalar W (CF), bcast y
    float acc[8];
    #pragma unroll
    for (int b = 0; b < 8; ++b) acc[b] = 0.f;
    #pragma unroll 2
    for (int g = 0; g < 8; ++g) {
        int ci0 = ci_base + g*4;
        const float* wp = W36 + ci0*36 + j;
        float w0 = wp[0], w1 = wp[36], w2 = wp[72], w3 = wp[108];
        #pragma unroll
        for (int b = 0; b < 8; ++b) {
            float4 yv = *(const float4*)(y_sm + b*512 + ci0);   // broadcast
            acc[b] = fmaf(yv.w, w3, fmaf(yv.z, w2,
                     fmaf(yv.y, w1, fmaf(yv.x, w0, acc[b]))));
        }
    }
    #pragma unroll
    for (int b = 0; b < 8; ++b) part[w5*264 + b*33 + j] = acc[b];
    __syncthreads();

    if (w5 < 8) {                  // warp = b
        int b = b0 + w5;
        float sacc = 0.f;
        #pragma unroll
        for (int e = 0; e < 16; ++e) sacc += part[e*264 + w5*33 + j];
        float Sinv = 1.f;
        if (mode != 0) {
            float sv = (j < 16) ? g_sp[b*512 + j*32 + o] : 0.f;
            #pragma unroll
            for (int s2 = 16; s2; s2 >>= 1) sv += __shfl_xor_sync(0xffffffffu, sv, s2);
            Sinv = 1.f / sv;
            if (mode == 1) {
                float mv = (j < 16) ? g_mp[b*512 + j*32 + o] : -1e30f;
                #pragma unroll
                for (int s2 = 16; s2; s2 >>= 1)
                    mv = fmaxf(mv, __shfl_xor_sync(0xffffffffu, mv, s2));
                if (j == 0) g_t[b*32 + o] = mv;
            }
        }
        float accv = sacc * Sinv;
        float mag_sq = accv*accv;
        #pragma unroll
        for (int s2 = 16; s2; s2 >>= 1) mag_sq += __shfl_xor_sync(0xffffffffu, mag_sq, s2);
        float mag = sqrtf(mag_sq) + 1e-11f;
        float a   = mag_sq / (1.f + mag_sq);
        float v   = accv * (a / mag);
        v_sm[w5*36 + j] = v;
        if (mode == 2) {
            out[(b*32 + o)*32 + j] = v;
            if (j == 0) out[32768 + b*32 + o] = a;
        }
    }
    if (mode == 2) return;
    __syncthreads();

    // z-loop: lane = (lb = j&7 -> b, lc = j>>3 -> ci offset); W rows bcast
    {
        int lb = j & 7, lc = j >> 3;
        float vp[32];
        const float4* vv = (const float4*)(v_sm + lb*36);      // bcast per lb
        #pragma unroll
        for (int k = 0; k < 8; ++k) {
            float4 u = vv[k];
            vp[4*k] = u.x; vp[4*k+1] = u.y; vp[4*k+2] = u.z; vp[4*k+3] = u.w;
        }
        float* zrow = g_z + ((b0 + lb)*32 + o)*512;
        #pragma unroll
        for (int it = 0; it < 8; ++it) {
            int ci = ci_base + it*4 + lc;
            const float4* wr = (const float4*)(W36 + ci*36);   // bcast x8
            float z = 0.f;
            #pragma unroll
            for (int k = 0; k < 8; ++k) {
                float4 wq = wr[k];
                z = fmaf(wq.x, vp[4*k], z);
                z = fmaf(wq.y, vp[4*k+1], z);
                z = fmaf(wq.z, vp[4*k+2], z);
                z = fmaf(wq.w, vp[4*k+3], z);
            }
            if (mode == 1) z += zrow[ci];
            zrow[ci] = z;
        }
    }
}

// ---------------------------------------------------------------------------
extern "C" void kernel_launch(void* const* d_in, const int* in_sizes, int n_in,
                              void* d_out, int out_size)
{
    const float* x = (const float*)d_in[0];
    const float* W = (const float*)(n_in > 1 ? d_in[1] : d_in[0]);
    for (int i = 0; i < n_in; ++i) {
        if (in_sizes[i] == 32*128*16*32)      x = (const float*)d_in[i];
        else if (in_sizes[i] == 16*32*32*32)  W = (const float*)d_in[i];
    }
    float* out = (float*)d_out;

    cudaFuncSetAttribute(k_s, cudaFuncAttributeMaxDynamicSharedMemorySize, SMEM_KS);
    cudaFuncSetAttribute(k_f, cudaFuncAttributeMaxDynamicSharedMemorySize, SMEM_KF);

    k_y0<<<256, 512>>>(x);
    k_s <<<128, 512, SMEM_KS>>>(W, 0, nullptr);   // v0, z_cum = z0
    k_f <<<128, 512, SMEM_KF>>>(x, 0, 1);         // y1, S + max partials
    k_s <<<128, 512, SMEM_KS>>>(W, 1, nullptr);   // v1, z_cum += z1, g_t
    k_f <<<128, 512, SMEM_KF>>>(x, 1, 0);         // y2, S
    k_s <<<128, 512, SMEM_KS>>>(W, 2, out);       // v2, a2 -> out
}